// round 16
// baseline (speedup 1.0000x reference)
#include <cuda_runtime.h>
#include <cuda_fp16.h>
#include <math.h>
#include <stdint.h>

#define MAXN 50000
#define MAXE 100000
#define MAXG 4096

typedef unsigned long long ull;

extern __shared__ __align__(1024) char smem_raw[];

// ---------------- device scratch -------------------------------------------
__device__ uint32_t g_h16[MAXN * 32]; // h packed half2 (MMA / P inputs)
__device__ float g_h32[MAXN * 64];    // h fp32 (exact GRU recurrence path)
__device__ float g_P[MAXN * 20];      // P[v,t] = h[v] . bond[t]
__device__ float g_sacc[MAXN * 20];   // zero invariant (node_mma re-zeroes)
__device__ float g_deg[MAXN];         // zero invariant (recip re-zeroes)
__device__ float g_cntb[MAXG];        // zero invariant (recip re-zeroes)
__device__ float g_rdeg[MAXN];
__device__ float g_rcnt[MAXG];
__device__ ull   g_pk_node[8064];     // gates 7168 | bond-S 512 | bond-P 384
__device__ ull   g_pk_init[3072];
__device__ float g_bias_node[320];
__device__ float g_bias_init[128];

__device__ __forceinline__ float sigf_(float x)   { return 1.0f / (1.0f + __expf(-x)); }
__device__ __forceinline__ float tanhf_(float x)  { return 2.0f * sigf_(2.0f * x) - 1.0f; }
__device__ __forceinline__ float leakyf_(float x) { return x > 0.0f ? x : 0.01f * x; }

__device__ __forceinline__ uint32_t h2_(float a, float b) {
    __half2 h = __floats2half2_rn(a, b);
    return *(uint32_t*)&h;
}

// m16n8k16 fp16 MMA, fp32 accum (portable PTX)
__device__ __forceinline__ void mma16(float* c, const uint32_t* a, ull b) {
    uint32_t b0 = (uint32_t)b, b1 = (uint32_t)(b >> 32);
    asm volatile(
        "mma.sync.aligned.m16n8k16.row.col.f32.f16.f16.f32 "
        "{%0,%1,%2,%3}, {%4,%5,%6,%7}, {%8,%9}, {%0,%1,%2,%3};"
        : "+f"(c[0]), "+f"(c[1]), "+f"(c[2]), "+f"(c[3])
        : "r"(a[0]), "r"(a[1]), "r"(a[2]), "r"(a[3]), "r"(b0), "r"(b1));
}

__device__ __forceinline__ void load_frag16(uint32_t* a, const uint4* sf4, int kk, int lane) {
    uint4 v = sf4[kk * 32 + lane];
    a[0] = v.x; a[1] = v.y; a[2] = v.z; a[3] = v.w;
}
__device__ __forceinline__ void fstore16(uint32_t* sf32, int rr, int f, uint32_t val) {
    int kk = f >> 4, kf = f & 15;
    int g = rr & 7, jr = (rr >> 3) & 1;
    int t = (kf >> 1) & 3;
    int j = jr + ((kf >= 8) ? 2 : 0);
    sf32[(kk * 32 + g * 4 + t) * 4 + j] = val;
}

#define A_ROOT 0
#define A_IHR  1
#define A_HHR  2
#define A_IHZ  3
#define A_HHZ  4
#define A_IHN  5
#define A_HHN  6
#define BOND_OFF 7168
#define PB_OFF   7680
#define NODE_SMEM   ((8064 + 2048 + 2048 + 1024) * 8 + 320 * 4)
#define INIT_SMEM   ((3456 + 4096 + 2048) * 8 + 128 * 4)

// ---------------- fused prologue: pack weights + deg + cnt ----------------------
__global__ void prep_kernel(
    const float* __restrict__ root, const float* __restrict__ cb,
    const float* __restrict__ wih, const float* __restrict__ whh,
    const float* __restrict__ bih, const float* __restrict__ bhh,
    const float* __restrict__ w1, const float* __restrict__ b1,
    const float* __restrict__ w2, const float* __restrict__ b2,
    const float* __restrict__ bondemb,
    const int* __restrict__ ei, const int* __restrict__ batch,
    int E, int n)
{
    int total = 11584 + E + n;
    for (int i = blockIdx.x * blockDim.x + threadIdx.x; i < total; i += gridDim.x * blockDim.x) {
        if (i < 7168) {
            int arr = i >> 10, rem = i & 1023;
            int hf = rem >> 9, nt = (rem >> 7) & 3, kk = (rem >> 5) & 3, ln = rem & 31;
            int nn = hf * 32 + nt * 8 + (ln >> 2);
            int k0 = kk * 16 + 2 * (ln & 3);
            float v0, v1, v2, v3;
            switch (arr) {
                case A_ROOT:
                    v0 = root[k0 * 64 + nn]; v1 = root[(k0 + 1) * 64 + nn];
                    v2 = root[(k0 + 8) * 64 + nn]; v3 = root[(k0 + 9) * 64 + nn]; break;
                case A_IHR: { const float* W = wih + (size_t)nn * 64;
                    v0 = W[k0]; v1 = W[k0 + 1]; v2 = W[k0 + 8]; v3 = W[k0 + 9]; } break;
                case A_HHR: { const float* W = whh + (size_t)nn * 64;
                    v0 = W[k0]; v1 = W[k0 + 1]; v2 = W[k0 + 8]; v3 = W[k0 + 9]; } break;
                case A_IHZ: { const float* W = wih + (size_t)(64 + nn) * 64;
                    v0 = W[k0]; v1 = W[k0 + 1]; v2 = W[k0 + 8]; v3 = W[k0 + 9]; } break;
                case A_HHZ: { const float* W = whh + (size_t)(64 + nn) * 64;
                    v0 = W[k0]; v1 = W[k0 + 1]; v2 = W[k0 + 8]; v3 = W[k0 + 9]; } break;
                case A_IHN: { const float* W = wih + (size_t)(128 + nn) * 64;
                    v0 = W[k0]; v1 = W[k0 + 1]; v2 = W[k0 + 8]; v3 = W[k0 + 9]; } break;
                default:    { const float* W = whh + (size_t)(128 + nn) * 64;
                    v0 = W[k0]; v1 = W[k0 + 1]; v2 = W[k0 + 8]; v3 = W[k0 + 9]; } break;
            }
            g_pk_node[i] = (ull)h2_(v0, v1) | ((ull)h2_(v2, v3) << 32);
        } else if (i < 7680) {
            int j = i - 7168;
            int hf = (j >> 8) & 1, nt = (j >> 6) & 3, kk = (j >> 5) & 1, ln = j & 31;
            int nn = hf * 32 + nt * 8 + (ln >> 2);
            int k0 = kk * 16 + 2 * (ln & 3);
            float v[4];
            #pragma unroll
            for (int d = 0; d < 4; d++) {
                int k = k0 + (d >> 1) * 8 + (d & 1);
                v[d] = (k < 20) ? bondemb[k * 64 + nn] : 0.0f;
            }
            g_pk_node[BOND_OFF + j] = (ull)h2_(v[0], v[1]) | ((ull)h2_(v[2], v[3]) << 32);
        } else if (i < 10752) {
            int j = i - 7680;
            if (j < 2048) {
                int hf = j >> 10, nt = (j >> 8) & 3, kk = (j >> 5) & 7, ln = j & 31;
                int nn = hf * 32 + nt * 8 + (ln >> 2);
                int k0 = kk * 16 + 2 * (ln & 3);
                const float* W = w1 + (size_t)nn * 128;
                g_pk_init[j] = (ull)h2_(W[k0], W[k0 + 1]) | ((ull)h2_(W[k0 + 8], W[k0 + 9]) << 32);
            } else {
                int jj = j - 2048;
                int hf = jj >> 9, nt = (jj >> 7) & 3, kk = (jj >> 5) & 3, ln = jj & 31;
                int nn = hf * 32 + nt * 8 + (ln >> 2);
                int k0 = kk * 16 + 2 * (ln & 3);
                const float* W = w2 + (size_t)nn * 64;
                g_pk_init[j] = (ull)h2_(W[k0], W[k0 + 1]) | ((ull)h2_(W[k0 + 8], W[k0 + 9]) << 32);
            }
        } else if (i < 11072) {
            int j = i - 10752;
            float v;
            if (j < 128)      v = bih[j] + bhh[j];
            else if (j < 192) v = bih[128 + (j - 128)];
            else if (j < 256) v = bhh[128 + (j - 192)];
            else              v = cb[j - 256];
            g_bias_node[j] = v;
        } else if (i < 11200) {
            int j = i - 11072;
            g_bias_init[j] = (j < 64) ? b1[j] : b2[j - 64];
        } else if (i < 11584) {
            int j = i - 11200;
            int ntg = j >> 7, kk = (j >> 5) & 3, ln = j & 31;
            int nn = ntg * 8 + (ln >> 2);
            int k0 = kk * 16 + 2 * (ln & 3);
            float v[4];
            #pragma unroll
            for (int d = 0; d < 4; d++) {
                int k = k0 + (d >> 1) * 8 + (d & 1);
                v[d] = (nn < 20) ? bondemb[nn * 64 + k] : 0.0f;
            }
            g_pk_node[PB_OFF + j] = (ull)h2_(v[0], v[1]) | ((ull)h2_(v[2], v[3]) << 32);
        } else if (i < 11584 + E) {
            atomicAdd(&g_deg[ei[E + (i - 11584)]], 1.0f);
        } else {
            atomicAdd(&g_cntb[batch[i - 11584 - E]], 1.0f);
        }
    }
}

__global__ void recip_kernel(int n, int G) {
    int i = blockIdx.x * blockDim.x + threadIdx.x;
    if (i < n) {
        g_rdeg[i] = 1.0f / fmaxf(g_deg[i], 1.0f);
        g_deg[i] = 0.0f;
    }
    if (i < G) {
        g_rcnt[i] = 1.0f / fmaxf(g_cntb[i], 1.0f);
        g_cntb[i] = 0.0f;
    }
}

// ---- P-pass: P strip from fragment tile -> g_P ----
__device__ __forceinline__ void p_pass(const uint4* strip, const ull* pkP,
                                       int half, int lane, int nb0, int p, int n)
{
    float pacc[8];
    #pragma unroll
    for (int t = 0; t < 8; t++) pacc[t] = 0.0f;
    const int nnt = (half == 0) ? 2 : 1;
    #pragma unroll
    for (int kk = 0; kk < 4; kk++) {
        uint32_t a[4];
        load_frag16(a, strip, kk, lane);
        for (int t = 0; t < nnt; t++) {
            int ntg = half * 2 + t;
            mma16(pacc + t * 4, a, pkP[ntg * 128 + kk * 32 + lane]);
        }
    }
    int arow = p * 16 + (lane >> 2);
    for (int t = 0; t < nnt; t++) {
        int ntg = half * 2 + t;
        int colp = ntg * 8 + (lane & 3) * 2;
        if (colp < 20) {
            #pragma unroll
            for (int qq = 0; qq < 2; qq++) {
                int gr = nb0 + arow + qq * 8;
                if (gr < n)
                    *(float2*)(g_P + (size_t)gr * 20 + colp) =
                        make_float2(pacc[t * 4 + qq * 2], pacc[t * 4 + qq * 2 + 1]);
            }
        }
    }
}

// ---------------- init MLP + P ---------------------------------------------------
__global__ void __launch_bounds__(512, 1) init_mma(
    const int* __restrict__ x, const int* __restrict__ batch,
    const float* __restrict__ vec, const float* __restrict__ blockemb, int n)
{
    ull* pk   = (ull*)smem_raw;        // [3456]: w1 2048 | w2 1024 | bond-P 384
    ull* in_f = pk + 3456;             // [8][512]
    ull* o1_f = in_f + 4096;           // [8][256]
    float* b1s = (float*)(o1_f + 2048);
    float* b2s = b1s + 64;

    const int tid  = threadIdx.x;
    const int w    = tid >> 5;
    const int lane = tid & 31;
    const int p    = w & 7;
    const int half = w >> 3;
    const int n0   = half * 32;

    for (int i = tid; i < 3072; i += 512) pk[i] = g_pk_init[i];
    for (int i = tid; i < 384; i += 512)  pk[3072 + i] = g_pk_node[PB_OFF + i];
    if (tid < 128) b1s[tid] = g_bias_init[tid];
    __syncthreads();

    const ull* w1pk = pk;
    const ull* w2pk = pk + 2048;
    const ull* pkP  = pk + 3072;

    const int ntiles = (n + 127) >> 7;
    for (int tile = blockIdx.x; tile < ntiles; tile += gridDim.x) {
        const int nb0 = tile << 7;
        {
            int row = tid >> 2, cpart = (tid & 3) * 32, gr = nb0 + row;
            int strip = row >> 4, rr = row & 15;
            uint32_t* sf = (uint32_t*)(in_f + strip * 512);
            if (gr < n) {
                const float* src = (cpart < 64)
                    ? (blockemb + (size_t)x[gr] * 64 + cpart)
                    : (vec + (size_t)batch[gr] * 64 + (cpart - 64));
                #pragma unroll
                for (int c = 0; c < 8; c++) {
                    float4 qv = ((const float4*)src)[c];
                    int f = cpart + c * 4;
                    fstore16(sf, rr, f,     h2_(qv.x, qv.y));
                    fstore16(sf, rr, f + 2, h2_(qv.z, qv.w));
                }
            } else {
                #pragma unroll
                for (int c = 0; c < 16; c++)
                    fstore16(sf, rr, cpart + c * 2, 0u);
            }
        }
        __syncthreads();

        float racc[16];
        #pragma unroll
        for (int t = 0; t < 16; t++) racc[t] = 0.0f;
        const uint4* istrip = (const uint4*)(in_f + p * 512);
        #pragma unroll
        for (int kk = 0; kk < 8; kk++) {
            uint32_t a[4];
            load_frag16(a, istrip, kk, lane);
            #pragma unroll
            for (int nt = 0; nt < 4; nt++)
                mma16(racc + nt * 4, a, w1pk[half * 1024 + nt * 256 + kk * 32 + lane]);
        }
        {
            uint32_t* of = (uint32_t*)(o1_f + p * 256);
            int rr0 = lane >> 2;
            #pragma unroll
            for (int nt = 0; nt < 4; nt++) {
                int colb = n0 + nt * 8 + (lane & 3) * 2;
                float c0 = b1s[colb], c1 = b1s[colb + 1];
                #pragma unroll
                for (int qq = 0; qq < 2; qq++)
                    fstore16(of, rr0 + qq * 8, colb,
                             h2_(leakyf_(racc[nt * 4 + qq * 2] + c0),
                                 leakyf_(racc[nt * 4 + qq * 2 + 1] + c1)));
            }
        }
        __syncthreads();

        float acc2[16];
        #pragma unroll
        for (int t = 0; t < 16; t++) acc2[t] = 0.0f;
        const uint4* ostrip = (const uint4*)(o1_f + p * 256);
        #pragma unroll
        for (int kk = 0; kk < 4; kk++) {
            uint32_t a[4];
            load_frag16(a, ostrip, kk, lane);
            #pragma unroll
            for (int nt = 0; nt < 4; nt++)
                mma16(acc2 + nt * 4, a, w2pk[half * 512 + nt * 128 + kk * 32 + lane]);
        }
        // h0 = acc2 + bias -> g_h32 (exact) + g_h16 (MMA copy); stash for P pass
        uint32_t hh[8];
        #pragma unroll
        for (int nt = 0; nt < 4; nt++) {
            int colb = n0 + nt * 8 + (lane & 3) * 2;
            float c0 = b2s[colb], c1 = b2s[colb + 1];
            #pragma unroll
            for (int qq = 0; qq < 2; qq++) {
                int gr = nb0 + p * 16 + (lane >> 2) + qq * 8;
                float vx = acc2[nt * 4 + qq * 2] + c0, vy = acc2[nt * 4 + qq * 2 + 1] + c1;
                uint32_t u = h2_(vx, vy);
                hh[nt * 2 + qq] = u;
                if (gr < n) {
                    g_h16[(size_t)gr * 32 + (colb >> 1)] = u;
                    *(float2*)(g_h32 + (size_t)gr * 64 + colb) = make_float2(vx, vy);
                }
            }
        }
        __syncthreads();
        {
            uint32_t* of = (uint32_t*)(o1_f + p * 256);
            int rr0 = lane >> 2;
            #pragma unroll
            for (int nt = 0; nt < 4; nt++) {
                int colb = n0 + nt * 8 + (lane & 3) * 2;
                #pragma unroll
                for (int qq = 0; qq < 2; qq++)
                    fstore16(of, rr0 + qq * 8, colb, hh[nt * 2 + qq]);
            }
        }
        __syncthreads();
        p_pass(ostrip, pkP, half, lane, nb0, p, n);
        __syncthreads();
    }
}

// ---------------- edge kernel: 1 thread/edge (R14 measured-best form) -----------
__global__ void edge_kernel(const int* __restrict__ ei, const int* __restrict__ ea, int E)
{
    int e = blockIdx.x * blockDim.x + threadIdx.x;
    if (e >= E) return;
    int src = ei[e], dst = ei[E + e];
    int2 a = ((const int2*)ea)[e];
    float s = __ldg(&g_P[(size_t)src * 20 + a.x]) * __ldg(&g_rdeg[dst]);
    atomicAdd(&g_sacc[(size_t)dst * 20 + a.y], s);
}

// ---------------- node kernel ----------------------------------------------------
__global__ void __launch_bounds__(512, 1) node_mma(
    const int* __restrict__ batch,
    float* __restrict__ out, int n, int last)
{
    ull* pk  = (ull*)smem_raw;          // [8064]
    ull* h_f = pk + 8064;
    ull* m_f = h_f + 2048;
    ull* s_f = m_f + 2048;
    float* br_s  = (float*)(s_f + 1024);
    float* bz_s  = br_s + 64;
    float* bin_s = bz_s + 64;
    float* bhn_s = bin_s + 64;
    float* cb_s  = bhn_s + 64;

    const int tid  = threadIdx.x;
    const int w    = tid >> 5;
    const int lane = tid & 31;
    // GEMM1 / P-pass mapping
    const int p    = w & 7;
    const int half = w >> 3;
    const int n0   = half * 32;
    // GEMM2 mapping: 32 rows x 16 cols per warp
    const int rs   = w & 3;
    const int cq   = w >> 2;
    const int hfq  = cq >> 1;
    const int ntb  = (cq & 1) * 2;

    for (int i = tid; i < 8064; i += 512) pk[i] = g_pk_node[i];
    if (tid < 320) br_s[tid] = g_bias_node[tid];
    __syncthreads();

    const int ntiles = (n + 127) >> 7;
    for (int tile = blockIdx.x; tile < ntiles; tile += gridDim.x) {
        const int nb0 = tile << 7;

        // H tile from g_h16 -> fragment smem (no cvt)
        {
            int row = tid >> 2, gr = nb0 + row;
            int strip = row >> 4, rr = row & 15;
            int c8 = (tid & 3) * 8;
            uint32_t* sf = (uint32_t*)(h_f + strip * 256);
            if (gr < n) {
                const uint4* hp = (const uint4*)(g_h16 + (size_t)gr * 32 + c8);
                uint4 u0 = hp[0], u1 = hp[1];
                int f = c8 * 2;
                fstore16(sf, rr, f,      u0.x); fstore16(sf, rr, f + 2,  u0.y);
                fstore16(sf, rr, f + 4,  u0.z); fstore16(sf, rr, f + 6,  u0.w);
                fstore16(sf, rr, f + 8,  u1.x); fstore16(sf, rr, f + 10, u1.y);
                fstore16(sf, rr, f + 12, u1.z); fstore16(sf, rr, f + 14, u1.w);
            } else {
                #pragma unroll
                for (int c = 0; c < 8; c++)
                    fstore16(sf, rr, c8 * 2 + c * 2, 0u);
            }
        }
        // S tile (20 -> pad 32); zero g_sacc for next step
        {
            int row = tid >> 2, gr = nb0 + row;
            int c0 = (tid & 3) * 8;
            int strip = row >> 4, rr = row & 15;
            uint32_t* sf = (uint32_t*)(s_f + strip * 128);
            float* sp = g_sacc + (size_t)gr * 20;
            #pragma unroll
            for (int c = 0; c < 4; c++) {
                int f = c0 + 2 * c;
                float va = 0.0f, vb = 0.0f;
                if (gr < n) {
                    if (f < 20)     { va = sp[f];     sp[f] = 0.0f; }
                    if (f + 1 < 20) { vb = sp[f + 1]; sp[f + 1] = 0.0f; }
                }
                fstore16(sf, rr, f, h2_(va, vb));
            }
        }
        __syncthreads();

        // early prefetch (GEMM2 mapping): h_old fp32 (exact), batch, rcnt
        float2 hof[8];
        float rc[4];
        int bg[4];
        #pragma unroll
        for (int rf = 0; rf < 2; rf++) {
            #pragma unroll
            for (int qq = 0; qq < 2; qq++) {
                int gr = nb0 + rs * 32 + rf * 16 + (lane >> 2) + qq * 8;
                int gi = rf * 2 + qq;
                bg[gi] = (last && gr < n) ? batch[gr] : 0;
                rc[gi] = last ? __ldg(&g_rcnt[bg[gi]]) : 1.0f;
                #pragma unroll
                for (int t = 0; t < 2; t++) {
                    int colb = cq * 16 + t * 8 + (lane & 3) * 2;
                    hof[rf * 4 + t * 2 + qq] = (gr < n)
                        ? *(const float2*)(g_h32 + (size_t)gr * 64 + colb)
                        : make_float2(0.0f, 0.0f);
                }
            }
        }

        const uint4* hstrip = (const uint4*)(h_f + p * 256);
        const uint4* sstrip = (const uint4*)(s_f + p * 128);

        // GEMM1: R = H @ root + S @ bond (16r x 32c mapping)
        float racc[16];
        #pragma unroll
        for (int t = 0; t < 16; t++) racc[t] = 0.0f;
        #pragma unroll
        for (int kk = 0; kk < 4; kk++) {
            uint32_t a[4];
            load_frag16(a, hstrip, kk, lane);
            #pragma unroll
            for (int nt = 0; nt < 4; nt++)
                mma16(racc + nt * 4, a, pk[A_ROOT * 1024 + half * 512 + nt * 128 + kk * 32 + lane]);
        }
        #pragma unroll
        for (int kk = 0; kk < 2; kk++) {
            uint32_t a[4];
            load_frag16(a, sstrip, kk, lane);
            #pragma unroll
            for (int nt = 0; nt < 4; nt++)
                mma16(racc + nt * 4, a, pk[BOND_OFF + half * 256 + nt * 64 + kk * 32 + lane]);
        }
        {
            uint32_t* mf = (uint32_t*)(m_f + p * 256);
            int rr0 = lane >> 2;
            #pragma unroll
            for (int nt = 0; nt < 4; nt++) {
                int colb = n0 + nt * 8 + (lane & 3) * 2;
                float cb0 = cb_s[colb], cb1 = cb_s[colb + 1];
                #pragma unroll
                for (int qq = 0; qq < 2; qq++)
                    fstore16(mf, rr0 + qq * 8, colb,
                             h2_(leakyf_(racc[nt * 4 + qq * 2] + cb0),
                                 leakyf_(racc[nt * 4 + qq * 2 + 1] + cb1)));
            }
        }
        __syncthreads();

        // GEMM2: gates, 32r x 16c warp tile
        float rg[16], zg[16], ig[16], hg[16];
        #pragma unroll
        for (int t = 0; t < 16; t++) { rg[t] = zg[t] = ig[t] = hg[t] = 0.0f; }
        #pragma unroll
        for (int kk = 0; kk < 4; kk++) {
            uint32_t aM[2][4], aH[2][4];
            #pragma unroll
            for (int rf = 0; rf < 2; rf++) {
                load_frag16(aM[rf], (const uint4*)(m_f + (2 * rs + rf) * 256), kk, lane);
                load_frag16(aH[rf], (const uint4*)(h_f + (2 * rs + rf) * 256), kk, lane);
            }
            #pragma unroll
            for (int t = 0; t < 2; t++) {
                int o = hfq * 512 + (ntb + t) * 128 + kk * 32 + lane;
                ull bir = pk[A_IHR * 1024 + o], bhr = pk[A_HHR * 1024 + o];
                ull biz = pk[A_IHZ * 1024 + o], bhz = pk[A_HHZ * 1024 + o];
                ull bin = pk[A_IHN * 1024 + o], bhn = pk[A_HHN * 1024 + o];
                #pragma unroll
                for (int rf = 0; rf < 2; rf++) {
                    float* rgp = rg + rf * 8 + t * 4;
                    float* zgp = zg + rf * 8 + t * 4;
                    float* igp = ig + rf * 8 + t * 4;
                    float* hgp = hg + rf * 8 + t * 4;
                    mma16(rgp, aM[rf], bir); mma16(rgp, aH[rf], bhr);
                    mma16(zgp, aM[rf], biz); mma16(zgp, aH[rf], bhz);
                    mma16(igp, aM[rf], bin); mma16(hgp, aH[rf], bhn);
                }
            }
        }

        // epilogue: GRU gate math; write h32+h16 (or pool)
        uint32_t o2h[8];
        #pragma unroll
        for (int rf = 0; rf < 2; rf++) {
            #pragma unroll
            for (int t = 0; t < 2; t++) {
                int colb = cq * 16 + t * 8 + (lane & 3) * 2;
                float br0 = br_s[colb], br1 = br_s[colb + 1];
                float bz0 = bz_s[colb], bz1 = bz_s[colb + 1];
                float bi0 = bin_s[colb], bi1 = bin_s[colb + 1];
                float bh0 = bhn_s[colb], bh1 = bhn_s[colb + 1];
                #pragma unroll
                for (int qq = 0; qq < 2; qq++) {
                    int gr = nb0 + rs * 32 + rf * 16 + (lane >> 2) + qq * 8;
                    int idx = rf * 8 + t * 4 + qq * 2;
                    int gi = rf * 2 + qq;
                    float2 ho = hof[rf * 4 + t * 2 + qq];
                    float r0v = sigf_(rg[idx]     + br0);
                    float r1v = sigf_(rg[idx + 1] + br1);
                    float z0v = sigf_(zg[idx]     + bz0);
                    float z1v = sigf_(zg[idx + 1] + bz1);
                    float n0v = tanhf_(ig[idx]     + bi0 + r0v * (hg[idx]     + bh0));
                    float n1v = tanhf_(ig[idx + 1] + bi1 + r1v * (hg[idx + 1] + bh1));
                    float ox = (1.0f - z0v) * n0v + z0v * ho.x;
                    float oy = (1.0f - z1v) * n1v + z1v * ho.y;
                    uint32_t u = h2_(ox, oy);
                    o2h[rf * 4 + t * 2 + qq] = u;
                    if (gr < n) {
                        if (last) {
                            float* op = out + (size_t)bg[gi] * 64 + colb;
                            asm volatile("red.global.add.v2.f32 [%0], {%1,%2};"
                                         :: "l"(op), "f"(ox * rc[gi]), "f"(oy * rc[gi]) : "memory");
                        } else {
                            g_h16[(size_t)gr * 32 + (colb >> 1)] = u;
                            *(float2*)(g_h32 + (size_t)gr * 64 + colb) = make_float2(ox, oy);
                        }
                    }
                }
            }
        }

        if (!last) {
            __syncthreads();   // all GEMM2 reads of h_f done
            {
                #pragma unroll
                for (int rf = 0; rf < 2; rf++) {
                    uint32_t* sf = (uint32_t*)(h_f + (2 * rs + rf) * 256);
                    int rr0 = lane >> 2;
                    #pragma unroll
                    for (int t = 0; t < 2; t++) {
                        int colb = cq * 16 + t * 8 + (lane & 3) * 2;
                        #pragma unroll
                        for (int qq = 0; qq < 2; qq++)
                            fstore16(sf, rr0 + qq * 8, colb, o2h[rf * 4 + t * 2 + qq]);
                    }
                }
            }
            __syncthreads();
            p_pass(hstrip, pk + PB_OFF, half, lane, nb0, p, n);
        }
        __syncthreads();
    }
}

// ---------------- launch ----------------------------------------------------------
extern "C" void kernel_launch(void* const* d_in, const int* in_sizes, int n_in,
                              void* d_out, int out_size)
{
    const int*   x        = (const int*)d_in[0];
    const int*   ei       = (const int*)d_in[1];
    const int*   ea       = (const int*)d_in[2];
    const int*   batch    = (const int*)d_in[3];
    const float* vec      = (const float*)d_in[4];
    const float* blockemb = (const float*)d_in[5];
    const float* bondemb  = (const float*)d_in[6];
    const float* w1       = (const float*)d_in[7];
    const float* b1       = (const float*)d_in[8];
    const float* w2       = (const float*)d_in[9];
    const float* b2       = (const float*)d_in[10];
    const float* root     = (const float*)d_in[11];
    const float* cb       = (const float*)d_in[12];
    const float* wih      = (const float*)d_in[13];
    const float* whh      = (const float*)d_in[14];
    const float* bih      = (const float*)d_in[15];
    const float* bhh      = (const float*)d_in[16];

    const int n = in_sizes[0];
    const int E = in_sizes[1] / 2;
    const int G = in_sizes[4] / 64;

    cudaFuncSetAttribute(init_mma, cudaFuncAttributeMaxDynamicSharedMemorySize, INIT_SMEM);
    cudaFuncSetAttribute(node_mma, cudaFuncAttributeMaxDynamicSharedMemorySize, NODE_SMEM);

    cudaMemsetAsync(d_out, 0, (size_t)out_size * sizeof(float));

    prep_kernel<<<296, 512>>>(root, cb, wih, whh, bih, bhh, w1, b1, w2, b2,
                              bondemb, ei, batch, E, n);
    recip_kernel<<<(n + 255) / 256, 256>>>(n, G);

    init_mma<<<148, 512, INIT_SMEM>>>(x, batch, vec, blockemb, n);

    for (int s = 0; s < 4; s++) {
        edge_kernel<<<(E + 255) / 256, 256>>>(ei, ea, E);
        node_mma<<<148, 512, NODE_SMEM>>>(batch, (float*)d_out, n, s == 3 ? 1 : 0);
    }
}